// round 5
// baseline (speedup 1.0000x reference)
#include <cuda_runtime.h>
#include <math.h>

#define MAXN 100000
#define MAXE 1200000
#define SCAN_B 512

// ---- scratch (static __device__, allocation-free) ----
__device__ __align__(16) float g_h[(size_t)MAXN * 64];   // h = x@W (row stride = Do)
__device__ float               g_as[MAXN];               // h @ a_src
__device__ float               g_ad[MAXN];               // h @ a_dst
__device__ __align__(16) float g_x[(size_t)MAXN * 64];   // layer output -> next input
__device__ int                 g_deg[MAXN];              // in-degree
__device__ int                 g_rowptr[MAXN];           // after scatter: rowptr[n] = end(n)
__device__ int                 g_csrc[MAXE];             // CSR src indices (grouped by dst)
__device__ int                 g_bsum[1024];             // scan partials

__device__ __forceinline__ float lrelu(float x) { return x > 0.f ? x : 0.2f * x; }

// ================= CSR build (integer atomics only) =================

__global__ void zero_deg(int N) {
    int i = blockIdx.x * blockDim.x + threadIdx.x;
    if (i < N) g_deg[i] = 0;
}

// edge_index is int32 (JAX x64 disabled downcasts the declared int64)
__global__ void hist_k(const int* __restrict__ ei, int E) {
    int i = blockIdx.x * blockDim.x + threadIdx.x;
    if (i < E) atomicAdd(&g_deg[ei[E + i]], 1);
}

__global__ void scan1(int N) {
    __shared__ int sh[SCAN_B];
    int tid = threadIdx.x;
    int i = blockIdx.x * SCAN_B + tid;
    int v = (i < N) ? g_deg[i] : 0;
    sh[tid] = v;
    __syncthreads();
    for (int o = 1; o < SCAN_B; o <<= 1) {
        int t = (tid >= o) ? sh[tid - o] : 0;
        __syncthreads();
        sh[tid] += t;
        __syncthreads();
    }
    if (i < N) g_rowptr[i] = sh[tid] - v;          // exclusive
    if (tid == SCAN_B - 1) g_bsum[blockIdx.x] = sh[tid];
}

__global__ void scan2(int nb) {
    __shared__ int sh[SCAN_B];
    int tid = threadIdx.x;
    int v = (tid < nb) ? g_bsum[tid] : 0;
    sh[tid] = v;
    __syncthreads();
    for (int o = 1; o < SCAN_B; o <<= 1) {
        int t = (tid >= o) ? sh[tid - o] : 0;
        __syncthreads();
        sh[tid] += t;
        __syncthreads();
    }
    if (tid < nb) g_bsum[tid] = sh[tid] - v;
}

__global__ void scan3(int N) {
    int i = blockIdx.x * blockDim.x + threadIdx.x;
    if (i < N) g_rowptr[i] += g_bsum[i / SCAN_B];
}

__global__ void scatter_k(const int* __restrict__ ei, int E) {
    int i = blockIdx.x * blockDim.x + threadIdx.x;
    if (i >= E) return;
    int s = ei[i];
    int d = ei[E + i];
    int pos = atomicAdd(&g_rowptr[d], 1);
    g_csrc[pos] = s;
}

// ================= K1: fused GEMM (Din=64) + attention scores =================
template <int Do, bool FROMG>
__global__ void gemm_attn(const float* __restrict__ xin, const float* __restrict__ W,
                          const float* __restrict__ a_s, const float* __restrict__ a_d,
                          int N) {
    const int Din = 64;
    __shared__ float Ws[Din * Do];
    __shared__ float xs[4][Din];
    __shared__ float s_as[4][2], s_ad[4][2];

    int col = threadIdx.x;
    int r   = threadIdx.y;
    int tid = r * 64 + col;
    for (int i = tid; i < Din * Do; i += 256) Ws[i] = W[i];

    int row = blockIdx.x * 4 + r;
    const float* src = FROMG ? g_x : xin;
    xs[r][col] = (row < N) ? src[(size_t)row * Din + col] : 0.f;
    __syncthreads();

    float acc = 0.f;
    if (col < Do) {
#pragma unroll
        for (int k = 0; k < Din; k++) acc += xs[r][k] * Ws[k * Do + col];
    }

    float ps = (col < Do) ? acc * a_s[col] : 0.f;
    float pd = (col < Do) ? acc * a_d[col] : 0.f;
#pragma unroll
    for (int o = 16; o > 0; o >>= 1) {
        ps += __shfl_down_sync(0xffffffffu, ps, o);
        pd += __shfl_down_sync(0xffffffffu, pd, o);
    }
    if ((col & 31) == 0) { s_as[r][col >> 5] = ps; s_ad[r][col >> 5] = pd; }
    __syncthreads();

    if (row < N) {
        if (col < Do) g_h[(size_t)row * Do + col] = acc;
        if (col == 0) {
            g_as[row] = s_as[r][0] + s_as[r][1];
            g_ad[row] = s_ad[r][0] + s_ad[r][1];
        }
    }
}

// ================= K2: per-node softmax + aggregate (warp per node) ==========
// MODE 0: relu(acc/den + b) -> g_x (GOUT=true)   Do = 64
// MODE 1: log_softmax(acc/den + b) -> out        Do = 40
template <int Do, int MODE, bool GOUT>
__global__ void agg(const float* __restrict__ b, float* __restrict__ out_arg, int N) {
    float* out = GOUT ? g_x : out_arg;
    int w    = (blockIdx.x * blockDim.x + threadIdx.x) >> 5;
    int lane = threadIdx.x & 31;
    if (w >= N) return;
    const int n = w;

    int end   = g_rowptr[n];
    int deg   = g_deg[n];
    int start = end - deg;
    float ad_n  = g_ad[n];
    float eself = lrelu(g_as[n] + ad_n);

    // --- phase A: segment max (self-loop included) ---
    float m = eself;
    for (int i = start + lane; i < end; i += 32)
        m = fmaxf(m, lrelu(g_as[g_csrc[i]] + ad_n));
#pragma unroll
    for (int o = 16; o > 0; o >>= 1)
        m = fmaxf(m, __shfl_xor_sync(0xffffffffu, m, o));

    // --- self contribution ---
    float exs   = expf(eself - m);
    float den_p = (lane == 0) ? exs : 0.f;
    float acc0  = exs * g_h[(size_t)n * Do + lane];
    float acc1  = (lane + 32 < Do) ? exs * g_h[(size_t)n * Do + lane + 32] : 0.f;

    // --- phase B: edges, chunked 32 at a time; shfl-broadcast (src, ex) ---
    for (int base = start; base < end; base += 32) {
        int i = base + lane;
        float ex = 0.f;
        int   s  = 0;
        if (i < end) {
            s  = g_csrc[i];
            ex = expf(lrelu(g_as[s] + ad_n) - m);
        }
        den_p += ex;
        int cnt = min(32, end - base);
        for (int j = 0; j < cnt; j++) {
            float exj = __shfl_sync(0xffffffffu, ex, j);
            int   sj  = __shfl_sync(0xffffffffu, s, j);
            acc0 += exj * g_h[(size_t)sj * Do + lane];
            if (lane + 32 < Do)
                acc1 += exj * g_h[(size_t)sj * Do + lane + 32];
        }
    }
#pragma unroll
    for (int o = 16; o > 0; o >>= 1)
        den_p += __shfl_xor_sync(0xffffffffu, den_p, o);
    float inv = 1.f / den_p;

    if (MODE == 0) {
        out[(size_t)n * 64 + lane]      = fmaxf(acc0 * inv + b[lane], 0.f);
        out[(size_t)n * 64 + lane + 32] = fmaxf(acc1 * inv + b[lane + 32], 0.f);
    } else {
        float v0 = acc0 * inv + b[lane];
        float v1 = (lane < 8) ? (acc1 * inv + b[lane + 32]) : -INFINITY;
        float mx = fmaxf(v0, v1);
#pragma unroll
        for (int o = 16; o > 0; o >>= 1)
            mx = fmaxf(mx, __shfl_xor_sync(0xffffffffu, mx, o));
        float sum = expf(v0 - mx) + ((lane < 8) ? expf(v1 - mx) : 0.f);
#pragma unroll
        for (int o = 16; o > 0; o >>= 1)
            sum += __shfl_xor_sync(0xffffffffu, sum, o);
        float ls = mx + logf(sum);
        out[(size_t)n * 40 + lane] = v0 - ls;
        if (lane < 8) out[(size_t)n * 40 + lane + 32] = v1 - ls;
    }
}

extern "C" void kernel_launch(void* const* d_in, const int* in_sizes, int n_in,
                              void* d_out, int out_size) {
    const int N = in_sizes[0] / 64;
    const int E = in_sizes[1] / 2;
    const float* x  = (const float*)d_in[0];
    const int*   ei = (const int*)d_in[1];     // int32 (JAX downcasts int64)

    const int TB = 256;
    int nblk  = (N + TB - 1) / TB;
    int eblk  = (E + TB - 1) / TB;
    int sblk  = (N + SCAN_B - 1) / SCAN_B;
    dim3 gblk(64, 4);
    int gemm_grid = (N + 3) / 4;
    int agg_grid  = (N + 7) / 8;

    // ---- CSR build (shared by all 3 layers) ----
    zero_deg<<<nblk, TB>>>(N);
    hist_k<<<eblk, TB>>>(ei, E);
    scan1<<<sblk, SCAN_B>>>(N);
    scan2<<<1, SCAN_B>>>(sblk);
    scan3<<<nblk, TB>>>(N);
    scatter_k<<<eblk, TB>>>(ei, E);

    // ---------- layer 0 ----------
    gemm_attn<64, false><<<gemm_grid, gblk>>>(x, (const float*)d_in[2],
                                              (const float*)d_in[3], (const float*)d_in[4], N);
    agg<64, 0, true><<<agg_grid, TB>>>((const float*)d_in[5], nullptr, N);

    // ---------- layer 1 ----------
    gemm_attn<64, true><<<gemm_grid, gblk>>>(nullptr, (const float*)d_in[6],
                                             (const float*)d_in[7], (const float*)d_in[8], N);
    agg<64, 0, true><<<agg_grid, TB>>>((const float*)d_in[9], nullptr, N);

    // ---------- layer 2 ----------
    gemm_attn<40, true><<<gemm_grid, gblk>>>(nullptr, (const float*)d_in[10],
                                             (const float*)d_in[11], (const float*)d_in[12], N);
    agg<40, 1, false><<<agg_grid, TB>>>((const float*)d_in[13], (float*)d_out, N);
}

// round 6
// speedup vs baseline: 1.1561x; 1.1561x over previous
#include <cuda_runtime.h>
#include <math.h>

#define MAXN 100000
#define MAXE 1200000
#define SCAN_B 512

// ---- scratch (static __device__, allocation-free) ----
__device__ __align__(16) float g_h[(size_t)MAXN * 64];   // h = x@W (row stride = Do)
__device__ float               g_as[MAXN];               // h @ a_src
__device__ float               g_ad[MAXN];               // h @ a_dst
__device__ __align__(16) float g_x[(size_t)MAXN * 64];   // layer output -> next input
__device__ int                 g_deg[MAXN];              // in-degree
__device__ int                 g_rowptr[MAXN];           // after scatter: rowptr[n] = end(n)
__device__ int                 g_csrc[MAXE];             // CSR src indices (grouped by dst)
__device__ int                 g_bsum[1024];             // scan partials

__device__ __forceinline__ float lrelu(float x) { return x > 0.f ? x : 0.2f * x; }

// ================= CSR build (integer atomics only) =================

__global__ void zero_deg(int N) {
    int i = blockIdx.x * blockDim.x + threadIdx.x;
    if (i < N) g_deg[i] = 0;
}

__global__ void hist_k(const int* __restrict__ ei, int E) {
    int i = blockIdx.x * blockDim.x + threadIdx.x;
    if (i < E) atomicAdd(&g_deg[ei[E + i]], 1);
}

__global__ void scan1(int N) {
    __shared__ int sh[SCAN_B];
    int tid = threadIdx.x;
    int i = blockIdx.x * SCAN_B + tid;
    int v = (i < N) ? g_deg[i] : 0;
    sh[tid] = v;
    __syncthreads();
    for (int o = 1; o < SCAN_B; o <<= 1) {
        int t = (tid >= o) ? sh[tid - o] : 0;
        __syncthreads();
        sh[tid] += t;
        __syncthreads();
    }
    if (i < N) g_rowptr[i] = sh[tid] - v;          // exclusive
    if (tid == SCAN_B - 1) g_bsum[blockIdx.x] = sh[tid];
}

__global__ void scan2(int nb) {
    __shared__ int sh[SCAN_B];
    int tid = threadIdx.x;
    int v = (tid < nb) ? g_bsum[tid] : 0;
    sh[tid] = v;
    __syncthreads();
    for (int o = 1; o < SCAN_B; o <<= 1) {
        int t = (tid >= o) ? sh[tid - o] : 0;
        __syncthreads();
        sh[tid] += t;
        __syncthreads();
    }
    if (tid < nb) g_bsum[tid] = sh[tid] - v;
}

__global__ void scan3(int N) {
    int i = blockIdx.x * blockDim.x + threadIdx.x;
    if (i < N) g_rowptr[i] += g_bsum[i / SCAN_B];
}

__global__ void scatter_k(const int* __restrict__ ei, int E) {
    int i = blockIdx.x * blockDim.x + threadIdx.x;
    if (i >= E) return;
    int s = ei[i];
    int d = ei[E + i];
    int pos = atomicAdd(&g_rowptr[d], 1);
    g_csrc[pos] = s;
}

// ================= K1: fused GEMM (Din=64) + attention scores =================
// 256 threads (64 x 4); 8 row-groups => 32 rows per block under ONE W smem load.
template <int Do, bool FROMG>
__global__ void gemm_attn(const float* __restrict__ xin, const float* __restrict__ W,
                          const float* __restrict__ a_s, const float* __restrict__ a_d,
                          int N) {
    const int Din = 64;
    const int RG  = 8;                 // row-groups of 4 rows
    __shared__ float Ws[Din * Do];
    __shared__ float xs[4][Din];
    __shared__ float s_as[4][2], s_ad[4][2];

    int col = threadIdx.x;             // 0..63
    int r   = threadIdx.y;             // 0..3
    int tid = r * 64 + col;
    for (int i = tid; i < Din * Do; i += 256) Ws[i] = W[i];

    float av = (col < Do) ? a_s[col] : 0.f;
    float dv = (col < Do) ? a_d[col] : 0.f;

    const float* src = FROMG ? g_x : xin;
    int row0 = blockIdx.x * (4 * RG);

#pragma unroll 1
    for (int g = 0; g < RG; g++) {
        int row = row0 + g * 4 + r;
        __syncthreads();               // protect xs/s_as from previous iteration
        xs[r][col] = (row < N) ? src[(size_t)row * Din + col] : 0.f;
        __syncthreads();

        float acc = 0.f;
        if (col < Do) {
#pragma unroll
            for (int k = 0; k < Din; k++) acc += xs[r][k] * Ws[k * Do + col];
        }

        float ps = acc * av;
        float pd = acc * dv;
#pragma unroll
        for (int o = 16; o > 0; o >>= 1) {
            ps += __shfl_down_sync(0xffffffffu, ps, o);
            pd += __shfl_down_sync(0xffffffffu, pd, o);
        }
        if ((col & 31) == 0) { s_as[r][col >> 5] = ps; s_ad[r][col >> 5] = pd; }
        __syncthreads();

        if (row < N) {
            if (col < Do) g_h[(size_t)row * Do + col] = acc;
            if (col == 0) {
                g_as[row] = s_as[r][0] + s_as[r][1];
                g_ad[row] = s_ad[r][0] + s_ad[r][1];
            }
        }
    }
}

// ================= K2: online softmax + aggregate (warp per node) ============
// Single pass over edges with flash-style running-max rescale.
// MODE 0: relu(acc/den + b) -> g_x   (Do = 64, GOUT = true)
// MODE 1: log_softmax(acc/den + b) -> out (Do = 40)
template <int Do, int MODE, bool GOUT>
__global__ void agg(const float* __restrict__ b, float* __restrict__ out_arg, int N) {
    float* out = GOUT ? g_x : out_arg;
    int w    = (blockIdx.x * blockDim.x + threadIdx.x) >> 5;
    int lane = threadIdx.x & 31;
    if (w >= N) return;
    const int n = w;

    int end   = g_rowptr[n];
    int start = end - g_deg[n];
    float ad_n = g_ad[n];

    // self-loop initializes running state: m = e_self, den = 1, acc = h[n]
    float m     = lrelu(g_as[n] + ad_n);
    float den_p = (lane == 0) ? 1.f : 0.f;           // per-lane partials
    float acc0  = g_h[(size_t)n * Do + lane];
    float acc1  = (lane + 32 < Do) ? g_h[(size_t)n * Do + lane + 32] : 0.f;

    for (int base = start; base < end; base += 32) {
        int i = base + lane;
        int   s = 0;
        float e = -INFINITY;
        if (i < end) {
            s = g_csrc[i];
            e = lrelu(g_as[s] + ad_n);
        }
        // chunk max -> running max update + rescale
        float cm = e;
#pragma unroll
        for (int o = 16; o > 0; o >>= 1)
            cm = fmaxf(cm, __shfl_xor_sync(0xffffffffu, cm, o));
        float mn = fmaxf(m, cm);
        float sc = expf(m - mn);
        den_p *= sc; acc0 *= sc; acc1 *= sc;
        m = mn;

        float ex = (i < end) ? expf(e - mn) : 0.f;
        den_p += ex;

        int cnt = min(32, end - base);
        for (int j = 0; j < cnt; j++) {
            float exj = __shfl_sync(0xffffffffu, ex, j);
            int   sj  = __shfl_sync(0xffffffffu, s, j);
            acc0 += exj * g_h[(size_t)sj * Do + lane];
            if (lane + 32 < Do)
                acc1 += exj * g_h[(size_t)sj * Do + lane + 32];
        }
    }
#pragma unroll
    for (int o = 16; o > 0; o >>= 1)
        den_p += __shfl_xor_sync(0xffffffffu, den_p, o);
    float inv = 1.f / den_p;

    if (MODE == 0) {
        out[(size_t)n * 64 + lane]      = fmaxf(acc0 * inv + b[lane], 0.f);
        out[(size_t)n * 64 + lane + 32] = fmaxf(acc1 * inv + b[lane + 32], 0.f);
    } else {
        float v0 = acc0 * inv + b[lane];
        float v1 = (lane < 8) ? (acc1 * inv + b[lane + 32]) : -INFINITY;
        float mx = fmaxf(v0, v1);
#pragma unroll
        for (int o = 16; o > 0; o >>= 1)
            mx = fmaxf(mx, __shfl_xor_sync(0xffffffffu, mx, o));
        float sum = expf(v0 - mx) + ((lane < 8) ? expf(v1 - mx) : 0.f);
#pragma unroll
        for (int o = 16; o > 0; o >>= 1)
            sum += __shfl_xor_sync(0xffffffffu, sum, o);
        float ls = mx + logf(sum);
        out[(size_t)n * 40 + lane] = v0 - ls;
        if (lane < 8) out[(size_t)n * 40 + lane + 32] = v1 - ls;
    }
}

extern "C" void kernel_launch(void* const* d_in, const int* in_sizes, int n_in,
                              void* d_out, int out_size) {
    const int N = in_sizes[0] / 64;
    const int E = in_sizes[1] / 2;
    const float* x  = (const float*)d_in[0];
    const int*   ei = (const int*)d_in[1];     // int32 (JAX downcasts int64)

    const int TB = 256;
    int nblk  = (N + TB - 1) / TB;
    int eblk  = (E + TB - 1) / TB;
    int sblk  = (N + SCAN_B - 1) / SCAN_B;
    dim3 gblk(64, 4);
    int gemm_grid = (N + 31) / 32;             // 32 rows per block
    int agg_grid  = (N + 7) / 8;               // 8 warps/block, warp per node

    // ---- CSR build (shared by all 3 layers) ----
    zero_deg<<<nblk, TB>>>(N);
    hist_k<<<eblk, TB>>>(ei, E);
    scan1<<<sblk, SCAN_B>>>(N);
    scan2<<<1, SCAN_B>>>(sblk);
    scan3<<<nblk, TB>>>(N);
    scatter_k<<<eblk, TB>>>(ei, E);

    // ---------- layer 0 ----------
    gemm_attn<64, false><<<gemm_grid, gblk>>>(x, (const float*)d_in[2],
                                              (const float*)d_in[3], (const float*)d_in[4], N);
    agg<64, 0, true><<<agg_grid, TB>>>((const float*)d_in[5], nullptr, N);

    // ---------- layer 1 ----------
    gemm_attn<64, true><<<gemm_grid, gblk>>>(nullptr, (const float*)d_in[6],
                                             (const float*)d_in[7], (const float*)d_in[8], N);
    agg<64, 0, true><<<agg_grid, TB>>>((const float*)d_in[9], nullptr, N);

    // ---------- layer 2 ----------
    gemm_attn<40, true><<<gemm_grid, gblk>>>(nullptr, (const float*)d_in[10],
                                             (const float*)d_in[11], (const float*)d_in[12], N);
    agg<40, 1, false><<<agg_grid, TB>>>((const float*)d_in[13], (float*)d_out, N);
}

// round 7
// speedup vs baseline: 1.1715x; 1.0133x over previous
#include <cuda_runtime.h>
#include <math.h>

#define MAXN 100000
#define MAXE 1200000
#define SCAN_B 512

// ---- scratch (static __device__, allocation-free) ----
__device__ __align__(16) float g_h[(size_t)MAXN * 64];   // h = x@W (row stride = Do)
__device__ float               g_as[MAXN];               // h @ a_src
__device__ float               g_ad[MAXN];               // h @ a_dst
__device__ __align__(16) float g_x[(size_t)MAXN * 64];   // layer output -> next input
__device__ int                 g_deg[MAXN];              // in-degree
__device__ int                 g_rowptr[MAXN];           // after scatter: rowptr[n] = end(n)
__device__ int                 g_csrc[MAXE];             // CSR src indices (grouped by dst)
__device__ int                 g_bsum[1024];             // scan partials

__device__ __forceinline__ float lrelu(float x) { return x > 0.f ? x : 0.2f * x; }

// ================= CSR build (integer atomics only) =================

__global__ void zero_deg(int N) {
    int i = blockIdx.x * blockDim.x + threadIdx.x;
    if (i < N) g_deg[i] = 0;
}

__global__ void hist_k(const int* __restrict__ ei, int E) {
    int i = blockIdx.x * blockDim.x + threadIdx.x;
    if (i < E) atomicAdd(&g_deg[ei[E + i]], 1);
}

__global__ void scan1(int N) {
    __shared__ int sh[SCAN_B];
    int tid = threadIdx.x;
    int i = blockIdx.x * SCAN_B + tid;
    int v = (i < N) ? g_deg[i] : 0;
    sh[tid] = v;
    __syncthreads();
    for (int o = 1; o < SCAN_B; o <<= 1) {
        int t = (tid >= o) ? sh[tid - o] : 0;
        __syncthreads();
        sh[tid] += t;
        __syncthreads();
    }
    if (i < N) g_rowptr[i] = sh[tid] - v;          // exclusive
    if (tid == SCAN_B - 1) g_bsum[blockIdx.x] = sh[tid];
}

__global__ void scan2(int nb) {
    __shared__ int sh[SCAN_B];
    int tid = threadIdx.x;
    int v = (tid < nb) ? g_bsum[tid] : 0;
    sh[tid] = v;
    __syncthreads();
    for (int o = 1; o < SCAN_B; o <<= 1) {
        int t = (tid >= o) ? sh[tid - o] : 0;
        __syncthreads();
        sh[tid] += t;
        __syncthreads();
    }
    if (tid < nb) g_bsum[tid] = sh[tid] - v;
}

__global__ void scan3(int N) {
    int i = blockIdx.x * blockDim.x + threadIdx.x;
    if (i < N) g_rowptr[i] += g_bsum[i / SCAN_B];
}

__global__ void scatter_k(const int* __restrict__ ei, int E) {
    int i = blockIdx.x * blockDim.x + threadIdx.x;
    if (i >= E) return;
    int s = ei[i];
    int d = ei[E + i];
    int pos = atomicAdd(&g_rowptr[d], 1);
    g_csrc[pos] = s;
}

// ================= K1: fused GEMM (Din=64) + attention scores =================
// 256 threads (64 x 4); 8 row-groups => 32 rows per block under ONE W smem load.
template <int Do, bool FROMG>
__global__ void gemm_attn(const float* __restrict__ xin, const float* __restrict__ W,
                          const float* __restrict__ a_s, const float* __restrict__ a_d,
                          int N) {
    const int Din = 64;
    const int RG  = 8;
    __shared__ float Ws[Din * Do];
    __shared__ float xs[4][Din];
    __shared__ float s_as[4][2], s_ad[4][2];

    int col = threadIdx.x;
    int r   = threadIdx.y;
    int tid = r * 64 + col;
    for (int i = tid; i < Din * Do; i += 256) Ws[i] = W[i];

    float av = (col < Do) ? a_s[col] : 0.f;
    float dv = (col < Do) ? a_d[col] : 0.f;

    const float* src = FROMG ? g_x : xin;
    int row0 = blockIdx.x * (4 * RG);

#pragma unroll 1
    for (int g = 0; g < RG; g++) {
        int row = row0 + g * 4 + r;
        __syncthreads();
        xs[r][col] = (row < N) ? src[(size_t)row * Din + col] : 0.f;
        __syncthreads();

        float acc = 0.f;
        if (col < Do) {
#pragma unroll
            for (int k = 0; k < Din; k++) acc += xs[r][k] * Ws[k * Do + col];
        }

        float ps = acc * av;
        float pd = acc * dv;
#pragma unroll
        for (int o = 16; o > 0; o >>= 1) {
            ps += __shfl_down_sync(0xffffffffu, ps, o);
            pd += __shfl_down_sync(0xffffffffu, pd, o);
        }
        if ((col & 31) == 0) { s_as[r][col >> 5] = ps; s_ad[r][col >> 5] = pd; }
        __syncthreads();

        if (row < N) {
            if (col < Do) g_h[(size_t)row * Do + col] = acc;
            if (col == 0) {
                g_as[row] = s_as[r][0] + s_as[r][1];
                g_ad[row] = s_ad[r][0] + s_ad[r][1];
            }
        }
    }
}

// ================= K2: softmax + aggregate (warp per node, float2 lanes) =====
// No running max: shift by the self-score (softmax is shift-invariant; scores
// are O(10), safe in fp32). Lane l owns columns 2l, 2l+1 (float2 per edge).
// MODE 0: relu(acc/den + b) -> g_x   (Do = 64, GOUT = true)
// MODE 1: log_softmax(acc/den + b) -> out (Do = 40)
template <int Do, int MODE, bool GOUT>
__global__ void agg(const float* __restrict__ b, float* __restrict__ out_arg, int N) {
    const unsigned FULL = 0xffffffffu;
    float* out = GOUT ? g_x : out_arg;
    int w    = (blockIdx.x * blockDim.x + threadIdx.x) >> 5;
    int lane = threadIdx.x & 31;
    if (w >= N) return;
    const int n = w;

    int end   = g_rowptr[n];
    int start = end - g_deg[n];
    float ad_n  = g_ad[n];
    float eself = lrelu(g_as[n] + ad_n);

    const int HL = Do / 2;               // lanes carrying data (32 or 20)
    bool act = (lane < HL);
    float2 acc = act ? *(const float2*)(g_h + (size_t)n * Do + 2 * lane)
                     : make_float2(0.f, 0.f);            // self contribution (ex=1)
    float den_p = (lane == 0) ? 1.f : 0.f;

    for (int base = start; base < end; base += 32) {
        int i = base + lane;
        int   s = 0;
        float ex = 0.f;
        if (i < end) {
            s  = g_csrc[i];
            ex = __expf(lrelu(g_as[s] + ad_n) - eself);
        }
        den_p += ex;

        int cnt = min(32, end - base);
        int j = 0;
        for (; j + 4 <= cnt; j += 4) {
            int   s0 = __shfl_sync(FULL, s, j),     s1 = __shfl_sync(FULL, s, j + 1);
            int   s2 = __shfl_sync(FULL, s, j + 2), s3 = __shfl_sync(FULL, s, j + 3);
            float e0 = __shfl_sync(FULL, ex, j),     e1 = __shfl_sync(FULL, ex, j + 1);
            float e2 = __shfl_sync(FULL, ex, j + 2), e3 = __shfl_sync(FULL, ex, j + 3);
            if (act) {
                float2 h0 = *(const float2*)(g_h + (size_t)s0 * Do + 2 * lane);
                float2 h1 = *(const float2*)(g_h + (size_t)s1 * Do + 2 * lane);
                float2 h2 = *(const float2*)(g_h + (size_t)s2 * Do + 2 * lane);
                float2 h3 = *(const float2*)(g_h + (size_t)s3 * Do + 2 * lane);
                acc.x += e0 * h0.x; acc.y += e0 * h0.y;
                acc.x += e1 * h1.x; acc.y += e1 * h1.y;
                acc.x += e2 * h2.x; acc.y += e2 * h2.y;
                acc.x += e3 * h3.x; acc.y += e3 * h3.y;
            }
        }
        for (; j < cnt; j++) {
            int   sj = __shfl_sync(FULL, s, j);
            float ej = __shfl_sync(FULL, ex, j);
            if (act) {
                float2 hj = *(const float2*)(g_h + (size_t)sj * Do + 2 * lane);
                acc.x += ej * hj.x; acc.y += ej * hj.y;
            }
        }
    }
#pragma unroll
    for (int o = 16; o > 0; o >>= 1)
        den_p += __shfl_xor_sync(FULL, den_p, o);
    float inv = 1.f / den_p;

    if (MODE == 0) {
        float2 bv = *(const float2*)(b + 2 * lane);
        float2 o2;
        o2.x = fmaxf(acc.x * inv + bv.x, 0.f);
        o2.y = fmaxf(acc.y * inv + bv.y, 0.f);
        *(float2*)(out + (size_t)n * 64 + 2 * lane) = o2;
    } else {
        float v0 = act ? (acc.x * inv + b[2 * lane])     : -INFINITY;
        float v1 = act ? (acc.y * inv + b[2 * lane + 1]) : -INFINITY;
        float mx = fmaxf(v0, v1);
#pragma unroll
        for (int o = 16; o > 0; o >>= 1)
            mx = fmaxf(mx, __shfl_xor_sync(FULL, mx, o));
        float sum = act ? (expf(v0 - mx) + expf(v1 - mx)) : 0.f;
#pragma unroll
        for (int o = 16; o > 0; o >>= 1)
            sum += __shfl_xor_sync(FULL, sum, o);
        float ls = mx + logf(sum);
        if (act) {
            out[(size_t)n * 40 + 2 * lane]     = v0 - ls;
            out[(size_t)n * 40 + 2 * lane + 1] = v1 - ls;
        }
    }
}

extern "C" void kernel_launch(void* const* d_in, const int* in_sizes, int n_in,
                              void* d_out, int out_size) {
    const int N = in_sizes[0] / 64;
    const int E = in_sizes[1] / 2;
    const float* x  = (const float*)d_in[0];
    const int*   ei = (const int*)d_in[1];     // int32 (JAX downcasts int64)

    const int TB = 256;
    int nblk  = (N + TB - 1) / TB;
    int eblk  = (E + TB - 1) / TB;
    int sblk  = (N + SCAN_B - 1) / SCAN_B;
    dim3 gblk(64, 4);
    int gemm_grid = (N + 31) / 32;
    int agg_grid  = (N + 7) / 8;

    // ---- CSR build (shared by all 3 layers) ----
    zero_deg<<<nblk, TB>>>(N);
    hist_k<<<eblk, TB>>>(ei, E);
    scan1<<<sblk, SCAN_B>>>(N);
    scan2<<<1, SCAN_B>>>(sblk);
    scan3<<<nblk, TB>>>(N);
    scatter_k<<<eblk, TB>>>(ei, E);

    // ---------- layer 0 ----------
    gemm_attn<64, false><<<gemm_grid, gblk>>>(x, (const float*)d_in[2],
                                              (const float*)d_in[3], (const float*)d_in[4], N);
    agg<64, 0, true><<<agg_grid, TB>>>((const float*)d_in[5], nullptr, N);

    // ---------- layer 1 ----------
    gemm_attn<64, true><<<gemm_grid, gblk>>>(nullptr, (const float*)d_in[6],
                                             (const float*)d_in[7], (const float*)d_in[8], N);
    agg<64, 0, true><<<agg_grid, TB>>>((const float*)d_in[9], nullptr, N);

    // ---------- layer 2 ----------
    gemm_attn<40, true><<<gemm_grid, gblk>>>(nullptr, (const float*)d_in[10],
                                             (const float*)d_in[11], (const float*)d_in[12], N);
    agg<40, 1, false><<<agg_grid, TB>>>((const float*)d_in[13], (float*)d_out, N);
}